// round 6
// baseline (speedup 1.0000x reference)
#include <cuda_runtime.h>

#define BN 8
#define HI 256
#define WI 256

__device__ float g_bufA[(size_t)BN * HI * WI * 64];
__device__ float g_bufB[(size_t)BN * HI * WI * 64];
__device__ float g_maskA[(size_t)BN * HI * WI];
__device__ float g_maskB[(size_t)BN * HI * WI];
__device__ float g_loss;

typedef unsigned long long ull;

// packed f32x2 helpers (SASS FFMA2 path — only reachable via PTX)
__device__ __forceinline__ ull pack2s(float v) {
    ull r; asm("mov.b64 %0, {%1, %1};" : "=l"(r) : "f"(v)); return r;
}
__device__ __forceinline__ ull pack2(float lo, float hi) {
    ull r; asm("mov.b64 %0, {%1, %2};" : "=l"(r) : "f"(lo), "f"(hi)); return r;
}
__device__ __forceinline__ void fma2(ull& d, ull a, ull b) {
    asm("fma.rn.f32x2 %0, %1, %2, %0;" : "+l"(d) : "l"(a), "l"(b));
}
__device__ __forceinline__ float2 unpk2(ull v) {
    float2 r; asm("mov.b64 {%0, %1}, %2;" : "=f"(r.x), "=f"(r.y) : "l"(v)); return r;
}

// gelu tanh-approx (jax approximate=True): 0.5x(1+tanh z) = x*sigmoid(2z)
__device__ __forceinline__ float gelu_f(float x) {
    float z2 = 1.5957691216057308f * (x + 0.044715f * x * x * x);
    float e = __expf(z2);
    return x * (1.0f - 1.0f / (e + 1.0f));
}

__global__ void zero_k() { g_loss = 0.0f; }
__global__ void fin_k(float* o) { o[0] = g_loss; }

// ---------- encoder stage 1: 3x3 conv 1->16 s1 SAME + chan-norm + gelu ----------
__global__ __launch_bounds__(128) void conv1_k(const float* __restrict__ img,
                                               const float* __restrict__ w,
                                               const float* __restrict__ bias,
                                               float* __restrict__ out) {
    __shared__ float ws[144];
    __shared__ float bs[16];
    for (int i = threadIdx.x; i < 144; i += 128) ws[i] = w[i];
    if (threadIdx.x < 16) bs[threadIdx.x] = bias[threadIdx.x];
    __syncthreads();

    int gid = blockIdx.x * 128 + threadIdx.x;   // BN*HI*WI threads exactly
    int b = gid >> 16;
    int oh = (gid >> 8) & 255;
    int ow = gid & 255;

    float acc[16];
#pragma unroll
    for (int c = 0; c < 16; c++) acc[c] = bs[c];
#pragma unroll
    for (int kh = 0; kh < 3; kh++) {
        int ih = oh + kh - 1;
        if (ih < 0 || ih >= HI) continue;
#pragma unroll
        for (int kw = 0; kw < 3; kw++) {
            int iw = ow + kw - 1;
            if (iw < 0 || iw >= WI) continue;
            float v = img[((size_t)(b * HI + ih) << 8) + iw];
            const float* wp = &ws[(kh * 3 + kw) * 16];
#pragma unroll
            for (int c = 0; c < 16; c++) acc[c] += v * wp[c];
        }
    }
    float mu = 0.f;
#pragma unroll
    for (int c = 0; c < 16; c++) mu += acc[c];
    mu *= (1.0f / 16.0f);
    float var = 0.f;
#pragma unroll
    for (int c = 0; c < 16; c++) { float d = acc[c] - mu; var += d * d; }
    var *= (1.0f / 16.0f);
    float rs = rsqrtf(var + 1e-6f);
    float* op = out + (size_t)gid * 16;
#pragma unroll
    for (int c = 0; c < 16; c++) op[c] = gelu_f((acc[c] - mu) * rs);
}

// ---------- stride-2 Conv_trio: 3x3 CIN->COUT s2 SAME (pad lo=0,hi=1) ----------
template <int CIN, int COUT>
__global__ __launch_bounds__(128) void trio_s2_k(const float* __restrict__ x,
                                                 float* __restrict__ out,
                                                 const float* __restrict__ w,
                                                 const float* __restrict__ bias,
                                                 int OH, int OW, int IH, int IW) {
    __shared__ float ws[3 * CIN * COUT];   // one kh slab [kw][ci][co]
    int gid = blockIdx.x * 128 + threadIdx.x;
    int total = BN * OH * OW;
    bool act = gid < total;
    int b = 0, oh = 0, ow = 0;
    if (act) {
        b = gid / (OH * OW);
        int r = gid - b * OH * OW;
        oh = r / OW;
        ow = r - oh * OW;
    }
    float acc[COUT];
#pragma unroll
    for (int c = 0; c < COUT; c++) acc[c] = 0.f;

    for (int kh = 0; kh < 3; kh++) {
        __syncthreads();
        for (int i = threadIdx.x; i < 3 * CIN * COUT; i += 128)
            ws[i] = w[kh * 3 * CIN * COUT + i];
        __syncthreads();
        if (!act) continue;
        int ih = oh * 2 + kh;
        if (ih >= IH) continue;
#pragma unroll
        for (int kw = 0; kw < 3; kw++) {
            int iw = ow * 2 + kw;
            if (iw >= IW) continue;
            const float4* xp = (const float4*)&x[(((size_t)b * IH + ih) * IW + iw) * CIN];
            const float* wp = &ws[kw * CIN * COUT];
#pragma unroll
            for (int c4 = 0; c4 < CIN / 4; c4++) {
                float4 xv = xp[c4];
                const float* w0 = &wp[(c4 * 4 + 0) * COUT];
                const float* w1 = &wp[(c4 * 4 + 1) * COUT];
                const float* w2 = &wp[(c4 * 4 + 2) * COUT];
                const float* w3 = &wp[(c4 * 4 + 3) * COUT];
#pragma unroll
                for (int c = 0; c < COUT; c++)
                    acc[c] += xv.x * w0[c] + xv.y * w1[c] + xv.z * w2[c] + xv.w * w3[c];
            }
        }
    }
    if (!act) return;
    float mu = 0.f;
#pragma unroll
    for (int c = 0; c < COUT; c++) { acc[c] += __ldg(&bias[c]); mu += acc[c]; }
    mu *= (1.0f / (float)COUT);
    float var = 0.f;
#pragma unroll
    for (int c = 0; c < COUT; c++) { float d = acc[c] - mu; var += d * d; }
    var *= (1.0f / (float)COUT);
    float rs = rsqrtf(var + 1e-6f);
    float* op = out + (size_t)gid * COUT;
#pragma unroll
    for (int c = 0; c < COUT; c++) op[c] = gelu_f((acc[c] - mu) * rs);
}

// ---------- conv_transpose 64->64, 3x3, stride 2 along DIM, + bias + gelu ----------
// Parity decomposition: output v even -> taps (cv=v/2-1,ks=0),(cv=v/2,ks=2);
// v odd -> (cv=(v-1)/2,ks=1). Non-strided dim u: standard pad-1 conv.
// Block: 64 u x 64 co, fixed v. 128 threads, each 4px x 8co, packed f32x2 FMA.
template <int DIM>
__global__ __launch_bounds__(128) void deconv_k(const float* __restrict__ x,
                                                float* __restrict__ y,
                                                const float* __restrict__ w,
                                                const float* __restrict__ bias,
                                                int OH, int OW) {
    __shared__ float w_s[4096];       // one tap [ci][co]
    __shared__ float in_s[64 * 67];   // [ci][j], j covers u0-1..u0+64, pitch 67

    const int IH = (DIM == 0) ? OH / 2 : OH;
    const int IW = (DIM == 0) ? OW : OW / 2;
    const int U = (DIM == 0) ? OW : OH;
    const size_t su  = (DIM == 0) ? 64 : (size_t)IW * 64;   // input stride along u
    const size_t sv  = (DIM == 0) ? (size_t)IW * 64 : 64;   // input stride along strided dim
    const size_t sou = (DIM == 0) ? 64 : (size_t)OW * 64;
    const size_t sov = (DIM == 0) ? (size_t)OW * 64 : 64;

    const int t = threadIdx.x;
    const int u0 = blockIdx.x * 64;
    const int v = blockIdx.y;
    const int b = blockIdx.z;
    const float* xb = x + (size_t)b * IH * IW * 64;
    float* yb = y + (size_t)b * OH * OW * 64;
    const int co0 = (t & 7) * 8;     // 8 co per thread
    const int px0 = (t >> 3) * 4;    // 4 px per thread

    ull acc[4][4];                    // [px][co-pair], each = 2 packed fp32
#pragma unroll
    for (int p = 0; p < 4; p++)
#pragma unroll
        for (int q = 0; q < 4; q++) acc[p][q] = 0ULL;   // bits(0,0) == (0.f,0.f)

    int scv[2], sks[2], ns = 0;
    if (v & 1) {
        scv[0] = v >> 1; sks[0] = 1; ns = 1;
    } else {
        if (v >= 2) { scv[0] = (v >> 1) - 1; sks[0] = 0; ns = 1; }
        scv[ns] = v >> 1; sks[ns] = 2; ns++;
    }

    for (int s = 0; s < ns; s++) {
        const int cv = scv[s];
        const int ks = sks[s];
        __syncthreads();
        for (int i = t; i < 66 * 64; i += 128) {
            int j = i >> 6, ci = i & 63;
            int iu = u0 - 1 + j;
            in_s[ci * 67 + j] = (iu >= 0 && iu < U)
                                    ? xb[(size_t)iu * su + (size_t)cv * sv + ci]
                                    : 0.f;
        }
        for (int kn = 0; kn < 3; kn++) {
            __syncthreads();
            {
                int tap = (DIM == 0) ? (ks * 3 + kn) : (kn * 3 + ks);
                const float4* sw = (const float4*)(w + (size_t)tap * 4096);
                float4* dw = (float4*)w_s;
                for (int i = t; i < 1024; i += 128) dw[i] = sw[i];
            }
            __syncthreads();
#pragma unroll 4
            for (int ci = 0; ci < 64; ci++) {
                ulonglong2 wa = *(const ulonglong2*)&w_s[ci * 64 + co0];
                ulonglong2 wb = *(const ulonglong2*)&w_s[ci * 64 + co0 + 4];
                const float* ip = &in_s[ci * 67 + px0 + kn];
#pragma unroll
                for (int p = 0; p < 4; p++) {
                    ull ax = pack2s(ip[p]);
                    fma2(acc[p][0], ax, wa.x);
                    fma2(acc[p][1], ax, wa.y);
                    fma2(acc[p][2], ax, wb.x);
                    fma2(acc[p][3], ax, wb.y);
                }
            }
        }
    }

    float4 bv0 = *(const float4*)&bias[co0];
    float4 bv1 = *(const float4*)&bias[co0 + 4];
#pragma unroll
    for (int p = 0; p < 4; p++) {
        int u = u0 + px0 + p;
        if (u >= U) continue;
        float2 r0 = unpk2(acc[p][0]);
        float2 r1 = unpk2(acc[p][1]);
        float2 r2 = unpk2(acc[p][2]);
        float2 r3 = unpk2(acc[p][3]);
        float4 o0, o1;
        o0.x = gelu_f(r0.x + bv0.x); o0.y = gelu_f(r0.y + bv0.y);
        o0.z = gelu_f(r1.x + bv0.z); o0.w = gelu_f(r1.y + bv0.w);
        o1.x = gelu_f(r2.x + bv1.x); o1.y = gelu_f(r2.y + bv1.y);
        o1.z = gelu_f(r3.x + bv1.z); o1.w = gelu_f(r3.y + bv1.w);
        float* op = &yb[(size_t)u * sou + (size_t)v * sov + co0];
        *(float4*)op = o0;
        *(float4*)(op + 4) = o1;
    }
}

// ---------- mask head: 3x3 conv 64->4 + softmax + mask update + loss ----------
__global__ __launch_bounds__(256) void mask_loss_k(const float* __restrict__ y,
                                                   const float* __restrict__ mw,
                                                   const float* __restrict__ mb,
                                                   const float* __restrict__ image,
                                                   const float* __restrict__ min_,
                                                   float* __restrict__ mout,
                                                   int hh, int ww, int dim,
                                                   int fh, int fw, float lw) {
    __shared__ float4 ws4[576];   // [tap*64+ci] -> weights for 4 outputs
    __shared__ float red[256];
    for (int i = threadIdx.x; i < 576; i += 256) ws4[i] = ((const float4*)mw)[i];
    __syncthreads();

    int gid = blockIdx.x * 256 + threadIdx.x;
    int total = BN * hh * ww;
    float local = 0.f;

    if (gid < total) {
        int b = gid / (hh * ww);
        int r = gid - b * hh * ww;
        int oh = r / ww;
        int ow = r - oh * ww;

        float4 mbv = *(const float4*)mb;
        ull m01 = pack2(mbv.x, mbv.y);
        ull m23 = pack2(mbv.z, mbv.w);
#pragma unroll
        for (int kh = 0; kh < 3; kh++) {
            int ph = oh + kh - 1;
            if (ph < 0 || ph >= hh) continue;
#pragma unroll
            for (int kw = 0; kw < 3; kw++) {
                int pw = ow + kw - 1;
                if (pw < 0 || pw >= ww) continue;
                const float4* a = (const float4*)&y[(((size_t)b * hh + ph) * ww + pw) * 64];
                const ulonglong2* wp2 = (const ulonglong2*)&ws4[(kh * 3 + kw) * 64];
#pragma unroll
                for (int c4 = 0; c4 < 16; c4++) {
                    float4 av = a[c4];
                    ulonglong2 w0 = wp2[c4 * 4 + 0];
                    ull ax = pack2s(av.x);
                    fma2(m01, ax, w0.x); fma2(m23, ax, w0.y);
                    ulonglong2 w1 = wp2[c4 * 4 + 1];
                    ull ay = pack2s(av.y);
                    fma2(m01, ay, w1.x); fma2(m23, ay, w1.y);
                    ulonglong2 w2 = wp2[c4 * 4 + 2];
                    ull az = pack2s(av.z);
                    fma2(m01, az, w2.x); fma2(m23, az, w2.y);
                    ulonglong2 w3 = wp2[c4 * 4 + 3];
                    ull aw = pack2s(av.w);
                    fma2(m01, aw, w3.x); fma2(m23, aw, w3.y);
                }
            }
        }
        float2 mlo = unpk2(m01);
        float2 mhi = unpk2(m23);
        // softmax over 4
        float mx = fmaxf(fmaxf(mlo.x, mlo.y), fmaxf(mhi.x, mhi.y));
        float e0 = __expf(mlo.x - mx), e1 = __expf(mlo.y - mx);
        float e2 = __expf(mhi.x - mx), e3 = __expf(mhi.y - mx);
        float inv = 1.0f / (e0 + e1 + e2 + e3);
        float p0 = e0 * inv, p1 = e1 * inv, p2 = e2 * inv, p3 = e3 * inv;
        float sprob = p1 + 2.0f * p2 + 3.0f * p3;
        float ent = -(p0 * __logf(p0 + 1e-8f) + p1 * __logf(p1 + 1e-8f) +
                      p2 * __logf(p2 + 1e-8f) + p3 * __logf(p3 + 1e-8f));
        // downsampled image
        float sum = 0.f;
        for (int u = 0; u < fh; u++)
            for (int vv = 0; vv < fw; vv++)
                sum += image[((size_t)(b * HI + oh * fh + u)) * WI + ow * fw + vv];
        float ds = sum / (float)(fh * fw);
        float d = sprob * (1.0f / 3.0f) - ds;
        local = lw * (ent + d * d) / (float)total;
        // masks = repeat(prev, 2, axis=dim+1) + 0.25 * sprob
        int ph2 = (dim == 0) ? (hh >> 1) : hh;
        int pw2 = (dim == 1) ? (ww >> 1) : ww;
        int moh = (dim == 0) ? (oh >> 1) : oh;
        int mow = (dim == 1) ? (ow >> 1) : ow;
        mout[gid] = min_[((size_t)b * ph2 + moh) * pw2 + mow] + 0.25f * sprob;
    }

    red[threadIdx.x] = local;
    __syncthreads();
    for (int st = 128; st > 0; st >>= 1) {
        if (threadIdx.x < st) red[threadIdx.x] += red[threadIdx.x + st];
        __syncthreads();
    }
    if (threadIdx.x == 0) atomicAdd(&g_loss, red[0]);
}

// ---------------------------------------------------------------------------
extern "C" void kernel_launch(void* const* d_in, const int* in_sizes, int n_in,
                              void* d_out, int out_size) {
    const float* image  = (const float*)d_in[0];
    // d_in[1] = dynamic_cfg (unused)
    const float* w1 = (const float*)d_in[2];
    const float* b1 = (const float*)d_in[3];
    const float* w2 = (const float*)d_in[4];
    const float* b2 = (const float*)d_in[5];
    const float* w3 = (const float*)d_in[6];
    const float* b3 = (const float*)d_in[7];
    const float* w4 = (const float*)d_in[8];
    const float* b4 = (const float*)d_in[9];
    const float* up_w = (const float*)d_in[10];
    const float* up_b = (const float*)d_in[11];
    const float* mask_w = (const float*)d_in[12];
    const float* mask_b = (const float*)d_in[13];
    const float* masks0 = (const float*)d_in[14];
    float* out = (float*)d_out;

    float *bufA, *bufB, *maskA, *maskB;
    cudaGetSymbolAddress((void**)&bufA, g_bufA);
    cudaGetSymbolAddress((void**)&bufB, g_bufB);
    cudaGetSymbolAddress((void**)&maskA, g_maskA);
    cudaGetSymbolAddress((void**)&maskB, g_maskB);

    zero_k<<<1, 1>>>();

    // encoder
    conv1_k<<<(BN * HI * WI) / 128, 128>>>(image, w1, b1, bufA);
    trio_s2_k<16, 16><<<(BN * 128 * 128) / 128, 128>>>(bufA, bufB, w2, b2, 128, 128, 256, 256);
    trio_s2_k<16, 32><<<(BN * 64 * 64) / 128, 128>>>(bufB, bufA, w3, b3, 64, 64, 128, 128);
    trio_s2_k<32, 64><<<(BN * 32 * 32) / 128, 128>>>(bufA, bufB, w4, b4, 32, 32, 64, 64);

    float* cur = bufB;
    float* nxt = bufA;
    const float* mcur = masks0;
    int h = 32, w = 32;
    const float LW[6] = {0.1f, 0.1f, 0.5f, 0.5f, 1.0f, 1.0f};

    for (int i = 0; i < 6; i++) {
        int dim = i % 2;
        if (dim == 0) h *= 2; else w *= 2;
        int U = (dim == 0) ? w : h;
        int V = (dim == 0) ? h : w;
        dim3 grid((U + 63) / 64, V, BN);
        if (dim == 0)
            deconv_k<0><<<grid, 128>>>(cur, nxt, up_w, up_b, h, w);
        else
            deconv_k<1><<<grid, 128>>>(cur, nxt, up_w, up_b, h, w);
        float* tmp = cur; cur = nxt; nxt = tmp;

        float* mout = (i == 5) ? (out + 1) : ((i % 2 == 0) ? maskA : maskB);
        int total = BN * h * w;
        mask_loss_k<<<(total + 255) / 256, 256>>>(cur, mask_w, mask_b, image, mcur,
                                                  mout, h, w, dim, HI / h, WI / w, LW[i]);
        mcur = mout;
    }

    fin_k<<<1, 1>>>(out);
}

// round 10
// speedup vs baseline: 1.7020x; 1.7020x over previous
#include <cuda_runtime.h>
#include <cuda_bf16.h>

#define BN 8
#define HI 256
#define WI 256

__device__ float g_bufA[(size_t)BN * HI * WI * 64];
__device__ float g_bufB[(size_t)BN * HI * WI * 64];
__device__ float g_maskA[(size_t)BN * HI * WI];
__device__ float g_maskB[(size_t)BN * HI * WI];
__device__ float g_loss;

// prepped deconv weights, bf16 hi/lo, layout [tap][co][ci] pitch 72 (zeros in pad)
// 9 taps * 64 co * 72 ci = 41472 bf16 = 5184 uint4 each
__device__ uint4 g_whi4[5184];
__device__ uint4 g_wlo4[5184];

// gelu tanh-approx (jax approximate=True): 0.5x(1+tanh z) = x*sigmoid(2z)
__device__ __forceinline__ float gelu_f(float x) {
    float z2 = 1.5957691216057308f * (x + 0.044715f * x * x * x);
    float e = __expf(z2);
    return x * (1.0f - 1.0f / (e + 1.0f));
}

__global__ void zero_k() { g_loss = 0.0f; }
__global__ void fin_k(float* o) { o[0] = g_loss; }

// ---------- weight prep: split fp32 -> bf16 hi/lo, transpose to [tap][co][ci] ----------
__global__ __launch_bounds__(256) void prep_w_k(const float* __restrict__ up_w) {
    int i = blockIdx.x * 256 + threadIdx.x;        // over 9*64*72
    if (i >= 9 * 64 * 72) return;
    int ci = i % 72;
    int co = (i / 72) % 64;
    int tap = i / (72 * 64);
    __nv_bfloat16 hi = __float2bfloat16(0.f), lo = __float2bfloat16(0.f);
    if (ci < 64) {
        float w = up_w[((size_t)tap * 64 + ci) * 64 + co];   // HWIO [kh][kw][ci][co]
        hi = __float2bfloat16(w);
        lo = __float2bfloat16(w - __bfloat162float(hi));
    }
    ((__nv_bfloat16*)g_whi4)[i] = hi;
    ((__nv_bfloat16*)g_wlo4)[i] = lo;
}

// ---------- encoder stage 1: 3x3 conv 1->16 s1 SAME + chan-norm + gelu ----------
__global__ __launch_bounds__(128) void conv1_k(const float* __restrict__ img,
                                               const float* __restrict__ w,
                                               const float* __restrict__ bias,
                                               float* __restrict__ out) {
    __shared__ float ws[144];
    __shared__ float bs[16];
    for (int i = threadIdx.x; i < 144; i += 128) ws[i] = w[i];
    if (threadIdx.x < 16) bs[threadIdx.x] = bias[threadIdx.x];
    __syncthreads();

    int gid = blockIdx.x * 128 + threadIdx.x;
    int b = gid >> 16;
    int oh = (gid >> 8) & 255;
    int ow = gid & 255;

    float acc[16];
#pragma unroll
    for (int c = 0; c < 16; c++) acc[c] = bs[c];
#pragma unroll
    for (int kh = 0; kh < 3; kh++) {
        int ih = oh + kh - 1;
        if (ih < 0 || ih >= HI) continue;
#pragma unroll
        for (int kw = 0; kw < 3; kw++) {
            int iw = ow + kw - 1;
            if (iw < 0 || iw >= WI) continue;
            float v = img[((size_t)(b * HI + ih) << 8) + iw];
            const float* wp = &ws[(kh * 3 + kw) * 16];
#pragma unroll
            for (int c = 0; c < 16; c++) acc[c] += v * wp[c];
        }
    }
    float mu = 0.f;
#pragma unroll
    for (int c = 0; c < 16; c++) mu += acc[c];
    mu *= (1.0f / 16.0f);
    float var = 0.f;
#pragma unroll
    for (int c = 0; c < 16; c++) { float d = acc[c] - mu; var += d * d; }
    var *= (1.0f / 16.0f);
    float rs = rsqrtf(var + 1e-6f);
    float* op = out + (size_t)gid * 16;
#pragma unroll
    for (int c = 0; c < 16; c++) op[c] = gelu_f((acc[c] - mu) * rs);
}

// ---------- stride-2 Conv_trio: 3x3 CIN->COUT s2 SAME ----------
template <int CIN, int COUT>
__global__ __launch_bounds__(128) void trio_s2_k(const float* __restrict__ x,
                                                 float* __restrict__ out,
                                                 const float* __restrict__ w,
                                                 const float* __restrict__ bias,
                                                 int OH, int OW, int IH, int IW) {
    __shared__ float ws[3 * CIN * COUT];
    int gid = blockIdx.x * 128 + threadIdx.x;
    int total = BN * OH * OW;
    bool act = gid < total;
    int b = 0, oh = 0, ow = 0;
    if (act) {
        b = gid / (OH * OW);
        int r = gid - b * OH * OW;
        oh = r / OW;
        ow = r - oh * OW;
    }
    float acc[COUT];
#pragma unroll
    for (int c = 0; c < COUT; c++) acc[c] = 0.f;

    for (int kh = 0; kh < 3; kh++) {
        __syncthreads();
        for (int i = threadIdx.x; i < 3 * CIN * COUT; i += 128)
            ws[i] = w[kh * 3 * CIN * COUT + i];
        __syncthreads();
        if (!act) continue;
        int ih = oh * 2 + kh;
        if (ih >= IH) continue;
#pragma unroll
        for (int kw = 0; kw < 3; kw++) {
            int iw = ow * 2 + kw;
            if (iw >= IW) continue;
            const float4* xp = (const float4*)&x[(((size_t)b * IH + ih) * IW + iw) * CIN];
            const float* wp = &ws[kw * CIN * COUT];
#pragma unroll
            for (int c4 = 0; c4 < CIN / 4; c4++) {
                float4 xv = xp[c4];
                const float* w0 = &wp[(c4 * 4 + 0) * COUT];
                const float* w1 = &wp[(c4 * 4 + 1) * COUT];
                const float* w2 = &wp[(c4 * 4 + 2) * COUT];
                const float* w3 = &wp[(c4 * 4 + 3) * COUT];
#pragma unroll
                for (int c = 0; c < COUT; c++)
                    acc[c] += xv.x * w0[c] + xv.y * w1[c] + xv.z * w2[c] + xv.w * w3[c];
            }
        }
    }
    if (!act) return;
    float mu = 0.f;
#pragma unroll
    for (int c = 0; c < COUT; c++) { acc[c] += __ldg(&bias[c]); mu += acc[c]; }
    mu *= (1.0f / (float)COUT);
    float var = 0.f;
#pragma unroll
    for (int c = 0; c < COUT; c++) { float d = acc[c] - mu; var += d * d; }
    var *= (1.0f / (float)COUT);
    float rs = rsqrtf(var + 1e-6f);
    float* op = out + (size_t)gid * COUT;
#pragma unroll
    for (int c = 0; c < COUT; c++) op[c] = gelu_f((acc[c] - mu) * rs);
}

// ---------- mma helpers ----------
__device__ __forceinline__ unsigned sptr(const void* p) {
    return (unsigned)__cvta_generic_to_shared(p);
}
__device__ __forceinline__ void ldsm4(unsigned* r, unsigned addr) {
    asm volatile("ldmatrix.sync.aligned.m8n8.x4.shared.b16 {%0,%1,%2,%3}, [%4];"
                 : "=r"(r[0]), "=r"(r[1]), "=r"(r[2]), "=r"(r[3]) : "r"(addr));
}
__device__ __forceinline__ void mma16816(float* d, const unsigned* a,
                                         unsigned b0, unsigned b1) {
    asm volatile(
        "mma.sync.aligned.m16n8k16.row.col.f32.bf16.bf16.f32 "
        "{%0,%1,%2,%3}, {%4,%5,%6,%7}, {%8,%9}, {%0,%1,%2,%3};"
        : "+f"(d[0]), "+f"(d[1]), "+f"(d[2]), "+f"(d[3])
        : "r"(a[0]), "r"(a[1]), "r"(a[2]), "r"(a[3]), "r"(b0), "r"(b1));
}

// ---------- conv_transpose 64->64 3x3 s2 along DIM + bias + gelu, tensor-core ----------
// Per (b, v) output row: out[u,co] = sum_{tap,ci} in[u+kn-1, cv_s, ci] * W[tap,ci,co].
// Parity: v even -> sources (cv=v/2-1,ks=0),(cv=v/2,ks=2); v odd -> (cv=(v-1)/2,ks=1).
// Block 256 thr = 8 warps; warp tile m16(u) x n32(co); split-bf16 (hi/lo) 3-term MMA.
#define PIT 72
template <int DIM>
__global__ __launch_bounds__(256) void deconv_mma_k(const float* __restrict__ x,
                                                    float* __restrict__ y,
                                                    const float* __restrict__ bias,
                                                    int OH, int OW) {
    __shared__ uint4 s_inhi4[66 * PIT * 2 / 16];   // 66 rows x 72 bf16
    __shared__ uint4 s_inlo4[66 * PIT * 2 / 16];
    __shared__ uint4 s_whi4[64 * PIT * 2 / 16];    // 64 co x 72 ci bf16
    __shared__ uint4 s_wlo4[64 * PIT * 2 / 16];
    __nv_bfloat16* inhi = (__nv_bfloat16*)s_inhi4;
    __nv_bfloat16* inlo = (__nv_bfloat16*)s_inlo4;

    const int IH = (DIM == 0) ? OH / 2 : OH;
    const int IW = (DIM == 0) ? OW : OW / 2;
    const int U = (DIM == 0) ? OW : OH;
    const size_t su  = (DIM == 0) ? 64 : (size_t)IW * 64;
    const size_t sv  = (DIM == 0) ? (size_t)IW * 64 : 64;
    const size_t sou = (DIM == 0) ? 64 : (size_t)OW * 64;
    const size_t sov = (DIM == 0) ? (size_t)OW * 64 : 64;

    const int t = threadIdx.x;
    const int lane = t & 31;
    const int warp = t >> 5;
    const int warpM = warp & 3;     // u tile: warpM*16
    const int warpN = warp >> 2;    // co tile: warpN*32
    const int u0 = blockIdx.x * 64;
    const int v = blockIdx.y;
    const int b = blockIdx.z;
    const float* xb = x + (size_t)b * IH * IW * 64;
    float* yb = y + (size_t)b * OH * OW * 64;

    float acc[4][4];                // [co n-group][frag reg]
#pragma unroll
    for (int g = 0; g < 4; g++)
#pragma unroll
        for (int r = 0; r < 4; r++) acc[g][r] = 0.f;

    int scv[2], sks[2], ns = 0;
    if (v & 1) {
        scv[0] = v >> 1; sks[0] = 1; ns = 1;
    } else {
        if (v >= 2) { scv[0] = (v >> 1) - 1; sks[0] = 0; ns = 1; }
        scv[ns] = v >> 1; sks[ns] = 2; ns++;
    }

    // per-lane ldmatrix address components
    const unsigned inhi_b = sptr(s_inhi4), inlo_b = sptr(s_inlo4);
    const unsigned whi_b = sptr(s_whi4), wlo_b = sptr(s_wlo4);
    const int a_row = warpM * 16 + (lane & 15);
    const int a_k8  = (lane >> 4) << 3;
    const int b_row = warpN * 32 + ((lane >> 4) << 3) + (lane & 7);
    const int b_k8  = ((lane >> 3) & 1) << 3;
    const unsigned boff0 = (unsigned)(b_row * PIT + b_k8) * 2;
    const unsigned boff1 = boff0 + 16 * PIT * 2;

    for (int s = 0; s < ns; s++) {
        const int cv = scv[s];
        const int ks = sks[s];
        __syncthreads();   // prior taps done before in_s overwrite
        for (int i = t; i < 66 * 64; i += 256) {
            int j = i >> 6, ci = i & 63;
            int iu = u0 - 1 + j;
            float val = (iu >= 0 && iu < U)
                            ? xb[(size_t)iu * su + (size_t)cv * sv + ci]
                            : 0.f;
            __nv_bfloat16 hi = __float2bfloat16(val);
            inhi[j * PIT + ci] = hi;
            inlo[j * PIT + ci] = __float2bfloat16(val - __bfloat162float(hi));
        }
        for (int kn = 0; kn < 3; kn++) {
            __syncthreads();   // staging visible / prior tap's mma done
            {
                int tap = (DIM == 0) ? (ks * 3 + kn) : (kn * 3 + ks);
                const uint4* srch = &g_whi4[tap * 576];
                const uint4* srcl = &g_wlo4[tap * 576];
                for (int i = t; i < 576; i += 256) {
                    s_whi4[i] = srch[i];
                    s_wlo4[i] = srcl[i];
                }
            }
            __syncthreads();

            const unsigned aoff = (unsigned)((a_row + kn) * PIT + a_k8) * 2;
#pragma unroll
            for (int c = 0; c < 4; c++) {       // ci chunks of 16
                const unsigned cb = c * 32;     // 16 bf16 = 32 bytes
                unsigned ah[4], al[4], bh0[4], bh1[4], bl0[4], bl1[4];
                ldsm4(ah, inhi_b + aoff + cb);
                ldsm4(al, inlo_b + aoff + cb);
                ldsm4(bh0, whi_b + boff0 + cb);
                ldsm4(bh1, whi_b + boff1 + cb);
                ldsm4(bl0, wlo_b + boff0 + cb);
                ldsm4(bl1, wlo_b + boff1 + cb);
                mma16816(acc[0], ah, bh0[0], bh0[1]);
                mma16816(acc[1], ah, bh0[2], bh0[3]);
                mma16816(acc[2], ah, bh1[0], bh1[1]);
                mma16816(acc[3], ah, bh1[2], bh1[3]);
                mma16816(acc[0], ah, bl0[0], bl0[1]);
                mma16816(acc[1], ah, bl0[2], bl0[3]);
                mma16816(acc[2], ah, bl1[0], bl1[1]);
                mma16816(acc[3], ah, bl1[2], bl1[3]);
                mma16816(acc[0], al, bh0[0], bh0[1]);
                mma16816(acc[1], al, bh0[2], bh0[3]);
                mma16816(acc[2], al, bh1[0], bh1[1]);
                mma16816(acc[3], al, bh1[2], bh1[3]);
            }
        }
    }

    // epilogue: frag (m16n8): d0,d1 -> row gid, cols tid2,+1; d2,d3 -> row gid+8
    const int gid = lane >> 2;
    const int tid2 = (lane & 3) * 2;
#pragma unroll
    for (int g = 0; g < 4; g++) {
        int co = warpN * 32 + g * 8 + tid2;
        float2 bv = *(const float2*)&bias[co];
        int u_a = u0 + warpM * 16 + gid;
        int u_b = u_a + 8;
        if (u_a < U) {
            float2 o;
            o.x = gelu_f(acc[g][0] + bv.x);
            o.y = gelu_f(acc[g][1] + bv.y);
            *(float2*)&yb[(size_t)u_a * sou + (size_t)v * sov + co] = o;
        }
        if (u_b < U) {
            float2 o;
            o.x = gelu_f(acc[g][2] + bv.x);
            o.y = gelu_f(acc[g][3] + bv.y);
            *(float2*)&yb[(size_t)u_b * sou + (size_t)v * sov + co] = o;
        }
    }
}

// ---------- mask head: 3x3 conv 64->4 + softmax + mask update + loss ----------
__global__ __launch_bounds__(256) void mask_loss_k(const float* __restrict__ y,
                                                   const float* __restrict__ mw,
                                                   const float* __restrict__ mb,
                                                   const float* __restrict__ image,
                                                   const float* __restrict__ min_,
                                                   float* __restrict__ mout,
                                                   int hh, int ww, int dim,
                                                   int fh, int fw, float lw) {
    __shared__ float4 ws4[576];
    __shared__ float red[256];
    for (int i = threadIdx.x; i < 576; i += 256) ws4[i] = ((const float4*)mw)[i];
    __syncthreads();

    int gid = blockIdx.x * 256 + threadIdx.x;
    int total = BN * hh * ww;
    float local = 0.f;

    if (gid < total) {
        int b = gid / (hh * ww);
        int r = gid - b * hh * ww;
        int oh = r / ww;
        int ow = r - oh * ww;

        float4 m = *(const float4*)mb;
#pragma unroll
        for (int kh = 0; kh < 3; kh++) {
            int ph = oh + kh - 1;
            if (ph < 0 || ph >= hh) continue;
#pragma unroll
            for (int kw = 0; kw < 3; kw++) {
                int pw = ow + kw - 1;
                if (pw < 0 || pw >= ww) continue;
                const float4* a = (const float4*)&y[(((size_t)b * hh + ph) * ww + pw) * 64];
                const float4* wp = &ws4[(kh * 3 + kw) * 64];
#pragma unroll
                for (int c4 = 0; c4 < 16; c4++) {
                    float4 av = a[c4];
                    float4 w0 = wp[c4 * 4 + 0];
                    m.x += av.x * w0.x; m.y += av.x * w0.y; m.z += av.x * w0.z; m.w += av.x * w0.w;
                    float4 w1 = wp[c4 * 4 + 1];
                    m.x += av.y * w1.x; m.y += av.y * w1.y; m.z += av.y * w1.z; m.w += av.y * w1.w;
                    float4 w2 = wp[c4 * 4 + 2];
                    m.x += av.z * w2.x; m.y += av.z * w2.y; m.z += av.z * w2.z; m.w += av.z * w2.w;
                    float4 w3 = wp[c4 * 4 + 3];
                    m.x += av.w * w3.x; m.y += av.w * w3.y; m.z += av.w * w3.z; m.w += av.w * w3.w;
                }
            }
        }
        float mx = fmaxf(fmaxf(m.x, m.y), fmaxf(m.z, m.w));
        float e0 = __expf(m.x - mx), e1 = __expf(m.y - mx);
        float e2 = __expf(m.z - mx), e3 = __expf(m.w - mx);
        float inv = 1.0f / (e0 + e1 + e2 + e3);
        float p0 = e0 * inv, p1 = e1 * inv, p2 = e2 * inv, p3 = e3 * inv;
        float sprob = p1 + 2.0f * p2 + 3.0f * p3;
        float ent = -(p0 * __logf(p0 + 1e-8f) + p1 * __logf(p1 + 1e-8f) +
                      p2 * __logf(p2 + 1e-8f) + p3 * __logf(p3 + 1e-8f));
        float sum = 0.f;
        for (int u = 0; u < fh; u++)
            for (int vv = 0; vv < fw; vv++)
                sum += image[((size_t)(b * HI + oh * fh + u)) * WI + ow * fw + vv];
        float ds = sum / (float)(fh * fw);
        float d = sprob * (1.0f / 3.0f) - ds;
        local = lw * (ent + d * d) / (float)total;
        int ph2 = (dim == 0) ? (hh >> 1) : hh;
        int pw2 = (dim == 1) ? (ww >> 1) : ww;
        int moh = (dim == 0) ? (oh >> 1) : oh;
        int mow = (dim == 1) ? (ow >> 1) : ow;
        mout[gid] = min_[((size_t)b * ph2 + moh) * pw2 + mow] + 0.25f * sprob;
    }

    red[threadIdx.x] = local;
    __syncthreads();
    for (int st = 128; st > 0; st >>= 1) {
        if (threadIdx.x < st) red[threadIdx.x] += red[threadIdx.x + st];
        __syncthreads();
    }
    if (threadIdx.x == 0) atomicAdd(&g_loss, red[0]);
}

// ---------------------------------------------------------------------------
extern "C" void kernel_launch(void* const* d_in, const int* in_sizes, int n_in,
                              void* d_out, int out_size) {
    const float* image  = (const float*)d_in[0];
    const float* w1 = (const float*)d_in[2];
    const float* b1 = (const float*)d_in[3];
    const float* w2 = (const float*)d_in[4];
    const float* b2 = (const float*)d_in[5];
    const float* w3 = (const float*)d_in[6];
    const float* b3 = (const float*)d_in[7];
    const float* w4 = (const float*)d_in[8];
    const float* b4 = (const float*)d_in[9];
    const float* up_w = (const float*)d_in[10];
    const float* up_b = (const float*)d_in[11];
    const float* mask_w = (const float*)d_in[12];
    const float* mask_b = (const float*)d_in[13];
    const float* masks0 = (const float*)d_in[14];
    float* out = (float*)d_out;

    float *bufA, *bufB, *maskA, *maskB;
    cudaGetSymbolAddress((void**)&bufA, g_bufA);
    cudaGetSymbolAddress((void**)&bufB, g_bufB);
    cudaGetSymbolAddress((void**)&maskA, g_maskA);
    cudaGetSymbolAddress((void**)&maskB, g_maskB);

    zero_k<<<1, 1>>>();
    prep_w_k<<<(9 * 64 * 72 + 255) / 256, 256>>>(up_w);

    conv1_k<<<(BN * HI * WI) / 128, 128>>>(image, w1, b1, bufA);
    trio_s2_k<16, 16><<<(BN * 128 * 128) / 128, 128>>>(bufA, bufB, w2, b2, 128, 128, 256, 256);
    trio_s2_k<16, 32><<<(BN * 64 * 64) / 128, 128>>>(bufB, bufA, w3, b3, 64, 64, 128, 128);
    trio_s2_k<32, 64><<<(BN * 32 * 32) / 128, 128>>>(bufA, bufB, w4, b4, 32, 32, 64, 64);

    float* cur = bufB;
    float* nxt = bufA;
    const float* mcur = masks0;
    int h = 32, w = 32;
    const float LW[6] = {0.1f, 0.1f, 0.5f, 0.5f, 1.0f, 1.0f};

    for (int i = 0; i < 6; i++) {
        int dim = i % 2;
        if (dim == 0) h *= 2; else w *= 2;
        int U = (dim == 0) ? w : h;
        int V = (dim == 0) ? h : w;
        dim3 grid((U + 63) / 64, V, BN);
        if (dim == 0)
            deconv_mma_k<0><<<grid, 256>>>(cur, nxt, up_b, h, w);
        else
            deconv_mma_k<1><<<grid, 256>>>(cur, nxt, up_b, h, w);
        float* tmp = cur; cur = nxt; nxt = tmp;

        float* mout = (i == 5) ? (out + 1) : ((i % 2 == 0) ? maskA : maskB);
        int total = BN * h * w;
        mask_loss_k<<<(total + 255) / 256, 256>>>(cur, mask_w, mask_b, image, mcur,
                                                  mout, h, w, dim, HI / h, WI / w, LW[i]);
        mcur = mout;
    }

    fin_k<<<1, 1>>>(out);
}